// round 1
// baseline (speedup 1.0000x reference)
#include <cuda_runtime.h>
#include <math.h>

#define B_   4
#define N_   1024
#define DIM_ 1024
#define H_   16
#define D_   64
#define SW_  256

#define BHND (B_*H_*N_*D_)

// Scratch (allocation-free rule: __device__ globals)
__device__ float g_Q[BHND];
__device__ float g_K[BHND];
__device__ float g_V[BHND];
__device__ float g_AO[B_*N_*H_*D_];   // [B, N, H, D] for proj GEMM

// ------------------------------------------------------------------
// Kernel 1: QKV GEMM (x[4096,1024] @ qkv_w^T[1024,3072]) fused with
// per-head LayerNorm (q,k) + RoPE, writing Q/K/V in [B,H,N,D].
// Block tile 128x64 (one head's D per column tile), BK=32,
// 256 threads, 8x4 register tile.
// ------------------------------------------------------------------
__global__ __launch_bounds__(256) void qkv_kernel(
    const float* __restrict__ x, const float* __restrict__ w,
    const float* __restrict__ qn_w, const float* __restrict__ qn_b,
    const float* __restrict__ kn_w, const float* __restrict__ kn_b)
{
    __shared__ __align__(16) float As[32][128];
    __shared__ __align__(16) float Bs[32][64];
    const int tid = threadIdx.x;
    const int tx = tid & 15, ty = tid >> 4;
    const int row0 = blockIdx.y * 128;
    const int col0 = blockIdx.x * 64;

    float acc[8][4];
    #pragma unroll
    for (int i = 0; i < 8; i++)
        #pragma unroll
        for (int j = 0; j < 4; j++) acc[i][j] = 0.f;

    for (int k0 = 0; k0 < DIM_; k0 += 32) {
        #pragma unroll
        for (int v = 0; v < 4; v++) {
            int idx = tid + v * 256;
            int r = idx >> 3, c = (idx & 7) << 2;
            float4 a = *(const float4*)(x + (size_t)(row0 + r) * DIM_ + k0 + c);
            As[c + 0][r] = a.x; As[c + 1][r] = a.y;
            As[c + 2][r] = a.z; As[c + 3][r] = a.w;
        }
        #pragma unroll
        for (int v = 0; v < 2; v++) {
            int idx = tid + v * 256;
            int r = idx >> 3, c = (idx & 7) << 2;
            float4 bv = *(const float4*)(w + (size_t)(col0 + r) * DIM_ + k0 + c);
            Bs[c + 0][r] = bv.x; Bs[c + 1][r] = bv.y;
            Bs[c + 2][r] = bv.z; Bs[c + 3][r] = bv.w;
        }
        __syncthreads();
        #pragma unroll 16
        for (int kk = 0; kk < 32; kk++) {
            float a[8], bb[4];
            float4 a0 = *(float4*)&As[kk][ty * 8];
            float4 a1 = *(float4*)&As[kk][ty * 8 + 4];
            a[0] = a0.x; a[1] = a0.y; a[2] = a0.z; a[3] = a0.w;
            a[4] = a1.x; a[5] = a1.y; a[6] = a1.z; a[7] = a1.w;
            float4 b0 = *(float4*)&Bs[kk][tx * 4];
            bb[0] = b0.x; bb[1] = b0.y; bb[2] = b0.z; bb[3] = b0.w;
            #pragma unroll
            for (int i = 0; i < 8; i++)
                #pragma unroll
                for (int j = 0; j < 4; j++)
                    acc[i][j] = fmaf(a[i], bb[j], acc[i][j]);
        }
        __syncthreads();
    }

    const int t = col0 / (H_ * D_);       // 0=q, 1=k, 2=v
    const int h = (col0 / D_) & (H_ - 1);
    const int d0 = tx * 4;

    if (t == 2) {
        #pragma unroll
        for (int r = 0; r < 8; r++) {
            int grow = row0 + ty * 8 + r;
            int b = grow >> 10, n = grow & 1023;
            *(float4*)(g_V + (size_t)((b * H_ + h) * N_ + n) * D_ + d0) =
                make_float4(acc[r][0], acc[r][1], acc[r][2], acc[r][3]);
        }
        return;
    }

    const float* lw = (t == 0) ? qn_w : kn_w;
    const float* lb = (t == 0) ? qn_b : kn_b;
    float* dst = (t == 0) ? g_Q : g_K;

    float wv[4], bv2[4], invf[4];
    #pragma unroll
    for (int j = 0; j < 4; j++) {
        wv[j]  = lw[d0 + j];
        bv2[j] = lb[d0 + j];
        int fi = (d0 + j) & 31;     // freq index = d % 32
        invf[j] = expf((float)fi * (-9.210340371976184f / 32.f)); // 10000^(-fi/32)
    }

    #pragma unroll
    for (int r = 0; r < 8; r++) {
        // LayerNorm over D=64 (row owned by 16 lanes in one warp half)
        float s = 0.f, ss = 0.f;
        #pragma unroll
        for (int j = 0; j < 4; j++) { s += acc[r][j]; ss += acc[r][j] * acc[r][j]; }
        #pragma unroll
        for (int o = 1; o < 16; o <<= 1) {
            s  += __shfl_xor_sync(0xffffffffu, s,  o);
            ss += __shfl_xor_sync(0xffffffffu, ss, o);
        }
        float mu   = s * (1.f / 64.f);
        float var  = ss * (1.f / 64.f) - mu * mu;
        float rstd = rsqrtf(var + 1e-5f);

        int grow = row0 + ty * 8 + r;
        int b = grow >> 10, n = grow & 1023;

        float nv[4], ov[4];
        #pragma unroll
        for (int j = 0; j < 4; j++)
            nv[j] = (acc[r][j] - mu) * rstd * wv[j] + bv2[j];

        // RoPE: partner dim d^32 lives on lane tx^8
        #pragma unroll
        for (int j = 0; j < 4; j++) {
            float other = __shfl_xor_sync(0xffffffffu, nv[j], 8);
            float ang = (float)n * invf[j];
            float sn, cs;
            sincosf(ang, &sn, &cs);
            ov[j] = (d0 < 32) ? (nv[j] * cs - other * sn)
                              : (nv[j] * cs + other * sn);
        }
        *(float4*)(dst + (size_t)((b * H_ + h) * N_ + n) * D_ + d0) =
            make_float4(ov[0], ov[1], ov[2], ov[3]);
    }
}

// ------------------------------------------------------------------
// Kernel 2: sliding-window attention with sink, flash-style.
// Block: 64 queries of one (b,h). 256 threads, 4x4 register tiles.
// ------------------------------------------------------------------
__global__ __launch_bounds__(256) void attn_kernel(const float* __restrict__ sinks)
{
    __shared__ __align__(16) float Qs[64][64];  // [d][i]
    __shared__ __align__(16) float KP[64][64];  // K as [d][j], reused as P [i][j]
    __shared__ __align__(16) float Vs[64][64];  // [j][d]

    const int bh = blockIdx.y;
    const int b = bh >> 4, h = bh & 15;
    const int q0 = blockIdx.x * 64;
    const int tid = threadIdx.x;
    const int tx = tid & 15, ty = tid >> 4;

    const float* Qg = g_Q + (size_t)((b * H_ + h) * N_) * D_;
    const float* Kg = g_K + (size_t)((b * H_ + h) * N_) * D_;
    const float* Vg = g_V + (size_t)((b * H_ + h) * N_) * D_;

    #pragma unroll
    for (int v = 0; v < 4; v++) {
        int idx = tid + v * 256;
        int r = idx >> 4, c = (idx & 15) << 2;
        float4 qv = *(const float4*)(Qg + (size_t)(q0 + r) * D_ + c);
        Qs[c + 0][r] = qv.x; Qs[c + 1][r] = qv.y;
        Qs[c + 2][r] = qv.z; Qs[c + 3][r] = qv.w;
    }

    const float snk = sinks[h];
    float m[4], dacc[4], o[4][4];
    #pragma unroll
    for (int i = 0; i < 4; i++) {
        m[i] = snk; dacc[i] = 1.f;   // sink logit folded into initial state
        #pragma unroll
        for (int j = 0; j < 4; j++) o[i][j] = 0.f;
    }

    const int kt_lo = (q0 >= SW_) ? ((q0 - SW_ + 1) >> 6) : 0;
    const int kt_hi = q0 >> 6;

    for (int kt = kt_lo; kt <= kt_hi; kt++) {
        const int k0 = kt << 6;
        __syncthreads();   // previous-iter P/V consumers done
        #pragma unroll
        for (int v = 0; v < 4; v++) {
            int idx = tid + v * 256;
            int r = idx >> 4, c = (idx & 15) << 2;
            float4 kv = *(const float4*)(Kg + (size_t)(k0 + r) * D_ + c);
            KP[c + 0][r] = kv.x; KP[c + 1][r] = kv.y;
            KP[c + 2][r] = kv.z; KP[c + 3][r] = kv.w;
            float4 vv = *(const float4*)(Vg + (size_t)(k0 + r) * D_ + c);
            *(float4*)&Vs[r][c] = vv;
        }
        __syncthreads();

        // S = Q @ K^T  (4x4 per thread)
        float s[4][4];
        #pragma unroll
        for (int i = 0; i < 4; i++)
            #pragma unroll
            for (int j = 0; j < 4; j++) s[i][j] = 0.f;

        #pragma unroll 8
        for (int kk = 0; kk < 64; kk++) {
            float4 qf = *(float4*)&Qs[kk][ty * 4];
            float4 kf = *(float4*)&KP[kk][tx * 4];
            float qa[4] = {qf.x, qf.y, qf.z, qf.w};
            float ka[4] = {kf.x, kf.y, kf.z, kf.w};
            #pragma unroll
            for (int i = 0; i < 4; i++)
                #pragma unroll
                for (int j = 0; j < 4; j++)
                    s[i][j] = fmaf(qa[i], ka[j], s[i][j]);
        }

        // mask + online softmax (per-row state replicated over 16 lanes)
        #pragma unroll
        for (int i = 0; i < 4; i++) {
            int gi = q0 + ty * 4 + i;
            #pragma unroll
            for (int j = 0; j < 4; j++) {
                int gj = k0 + tx * 4 + j;
                bool ok = (gj <= gi) && (gj > gi - SW_);
                s[i][j] = ok ? s[i][j] * 0.125f : -1e30f;
            }
            float rm = fmaxf(fmaxf(s[i][0], s[i][1]), fmaxf(s[i][2], s[i][3]));
            #pragma unroll
            for (int off = 1; off < 16; off <<= 1)
                rm = fmaxf(rm, __shfl_xor_sync(0xffffffffu, rm, off));
            float mn = fmaxf(m[i], rm);
            float sc = __expf(m[i] - mn);
            m[i] = mn; dacc[i] *= sc;
            #pragma unroll
            for (int j = 0; j < 4; j++) o[i][j] *= sc;
            float rs = 0.f;
            #pragma unroll
            for (int j = 0; j < 4; j++) {
                s[i][j] = __expf(s[i][j] - mn);
                rs += s[i][j];
            }
            #pragma unroll
            for (int off = 1; off < 16; off <<= 1)
                rs += __shfl_xor_sync(0xffffffffu, rs, off);
            dacc[i] += rs;
        }

        __syncthreads();   // all lanes done reading K from KP
        #pragma unroll
        for (int i = 0; i < 4; i++)
            *(float4*)&KP[ty * 4 + i][tx * 4] =
                make_float4(s[i][0], s[i][1], s[i][2], s[i][3]);  // P[i][j]
        __syncthreads();

        // O += P @ V
        #pragma unroll 4
        for (int j0 = 0; j0 < 64; j0 += 4) {
            float4 vv0 = *(float4*)&Vs[j0 + 0][tx * 4];
            float4 vv1 = *(float4*)&Vs[j0 + 1][tx * 4];
            float4 vv2 = *(float4*)&Vs[j0 + 2][tx * 4];
            float4 vv3 = *(float4*)&Vs[j0 + 3][tx * 4];
            #pragma unroll
            for (int i = 0; i < 4; i++) {
                float4 pv = *(float4*)&KP[ty * 4 + i][j0];
                o[i][0] = fmaf(pv.x, vv0.x, fmaf(pv.y, vv1.x, fmaf(pv.z, vv2.x, fmaf(pv.w, vv3.x, o[i][0]))));
                o[i][1] = fmaf(pv.x, vv0.y, fmaf(pv.y, vv1.y, fmaf(pv.z, vv2.y, fmaf(pv.w, vv3.y, o[i][1]))));
                o[i][2] = fmaf(pv.x, vv0.z, fmaf(pv.y, vv1.z, fmaf(pv.z, vv2.z, fmaf(pv.w, vv3.z, o[i][2]))));
                o[i][3] = fmaf(pv.x, vv0.w, fmaf(pv.y, vv1.w, fmaf(pv.z, vv2.w, fmaf(pv.w, vv3.w, o[i][3]))));
            }
        }
    }

    #pragma unroll
    for (int i = 0; i < 4; i++) {
        float inv = 1.f / dacc[i];
        int gi = q0 + ty * 4 + i;
        *(float4*)(g_AO + (size_t)((b * N_ + gi) * H_ + h) * D_ + tx * 4) =
            make_float4(o[i][0] * inv, o[i][1] * inv, o[i][2] * inv, o[i][3] * inv);
    }
}

// ------------------------------------------------------------------
// Kernel 3: output projection GEMM (g_AO[4096,1024] @ proj_w^T) + bias
// ------------------------------------------------------------------
__global__ __launch_bounds__(256) void proj_kernel(
    const float* __restrict__ w, const float* __restrict__ bias,
    float* __restrict__ out)
{
    __shared__ __align__(16) float As[32][128];
    __shared__ __align__(16) float Bs[32][64];
    const int tid = threadIdx.x;
    const int tx = tid & 15, ty = tid >> 4;
    const int row0 = blockIdx.y * 128;
    const int col0 = blockIdx.x * 64;

    float acc[8][4];
    #pragma unroll
    for (int i = 0; i < 8; i++)
        #pragma unroll
        for (int j = 0; j < 4; j++) acc[i][j] = 0.f;

    const float* A = g_AO;
    for (int k0 = 0; k0 < DIM_; k0 += 32) {
        #pragma unroll
        for (int v = 0; v < 4; v++) {
            int idx = tid + v * 256;
            int r = idx >> 3, c = (idx & 7) << 2;
            float4 a = *(const float4*)(A + (size_t)(row0 + r) * DIM_ + k0 + c);
            As[c + 0][r] = a.x; As[c + 1][r] = a.y;
            As[c + 2][r] = a.z; As[c + 3][r] = a.w;
        }
        #pragma unroll
        for (int v = 0; v < 2; v++) {
            int idx = tid + v * 256;
            int r = idx >> 3, c = (idx & 7) << 2;
            float4 bv = *(const float4*)(w + (size_t)(col0 + r) * DIM_ + k0 + c);
            Bs[c + 0][r] = bv.x; Bs[c + 1][r] = bv.y;
            Bs[c + 2][r] = bv.z; Bs[c + 3][r] = bv.w;
        }
        __syncthreads();
        #pragma unroll 16
        for (int kk = 0; kk < 32; kk++) {
            float a[8], bb[4];
            float4 a0 = *(float4*)&As[kk][ty * 8];
            float4 a1 = *(float4*)&As[kk][ty * 8 + 4];
            a[0] = a0.x; a[1] = a0.y; a[2] = a0.z; a[3] = a0.w;
            a[4] = a1.x; a[5] = a1.y; a[6] = a1.z; a[7] = a1.w;
            float4 b0 = *(float4*)&Bs[kk][tx * 4];
            bb[0] = b0.x; bb[1] = b0.y; bb[2] = b0.z; bb[3] = b0.w;
            #pragma unroll
            for (int i = 0; i < 8; i++)
                #pragma unroll
                for (int j = 0; j < 4; j++)
                    acc[i][j] = fmaf(a[i], bb[j], acc[i][j]);
        }
        __syncthreads();
    }

    float bb0 = bias[col0 + tx * 4 + 0];
    float bb1 = bias[col0 + tx * 4 + 1];
    float bb2 = bias[col0 + tx * 4 + 2];
    float bb3 = bias[col0 + tx * 4 + 3];
    #pragma unroll
    for (int r = 0; r < 8; r++) {
        int grow = row0 + ty * 8 + r;
        *(float4*)(out + (size_t)grow * DIM_ + col0 + tx * 4) =
            make_float4(acc[r][0] + bb0, acc[r][1] + bb1,
                        acc[r][2] + bb2, acc[r][3] + bb3);
    }
}

extern "C" void kernel_launch(void* const* d_in, const int* in_sizes, int n_in,
                              void* d_out, int out_size)
{
    const float* x      = (const float*)d_in[0];
    const float* qkv_w  = (const float*)d_in[1];
    const float* qn_w   = (const float*)d_in[2];
    const float* qn_b   = (const float*)d_in[3];
    const float* kn_w   = (const float*)d_in[4];
    const float* kn_b   = (const float*)d_in[5];
    const float* sinks  = (const float*)d_in[6];
    const float* proj_w = (const float*)d_in[7];
    const float* proj_b = (const float*)d_in[8];
    float* out = (float*)d_out;

    qkv_kernel<<<dim3(48, 32), 256>>>(x, qkv_w, qn_w, qn_b, kn_w, kn_b);
    attn_kernel<<<dim3(16, 64), 256>>>(sinks);
    proj_kernel<<<dim3(16, 32), 256>>>(proj_w, proj_b, out);
}

// round 3
// speedup vs baseline: 1.9623x; 1.9623x over previous
#include <cuda_runtime.h>
#include <cuda_bf16.h>
#include <math.h>
#include <cstdint>

#define B_   4
#define N_   1024
#define DIM_ 1024
#define H_   16
#define D_   64
#define SW_  256
#define BHND (B_*H_*N_*D_)

__device__ float g_Q[BHND];
__device__ float g_K[BHND];
__device__ float g_V[BHND];
__device__ float g_AO[BHND];   // [B, N, H, D] for proj GEMM

// ---------------- helpers ----------------
__device__ __forceinline__ void split2(float x, float y, unsigned &hi, unsigned &lo) {
    __nv_bfloat16 hx = __float2bfloat16(x), hy = __float2bfloat16(y);
    float rx = x - __bfloat162float(hx);
    float ry = y - __bfloat162float(hy);
    __nv_bfloat16 lx = __float2bfloat16(rx), ly = __float2bfloat16(ry);
    hi = ((unsigned)__bfloat16_as_ushort(hy) << 16) | (unsigned)__bfloat16_as_ushort(hx);
    lo = ((unsigned)__bfloat16_as_ushort(ly) << 16) | (unsigned)__bfloat16_as_ushort(lx);
}

__device__ __forceinline__ void mma16816(float* c, unsigned a0, unsigned a1,
                                         unsigned a2, unsigned a3,
                                         unsigned b0, unsigned b1) {
    asm volatile(
        "mma.sync.aligned.m16n8k16.row.col.f32.bf16.bf16.f32 "
        "{%0,%1,%2,%3}, {%4,%5,%6,%7}, {%8,%9}, {%0,%1,%2,%3};"
        : "+f"(c[0]), "+f"(c[1]), "+f"(c[2]), "+f"(c[3])
        : "r"(a0), "r"(a1), "r"(a2), "r"(a3), "r"(b0), "r"(b1));
}

// SMEM tile layout (words): per stage 10240 words (40960 B)
//   A_HI @0, A_LO @2560, B_HI @5120, B_LO @7680; row stride 20 words (K=32 bf16 + pad)
#define SWRD   10240
#define O_ALO  2560
#define O_BHI  5120
#define O_BLO  7680
#define GEMM_SMEM 81920   // 2 stages; epilogue stage (128x132 f32 = 67584B) reuses it

// ------------------------------------------------------------------
// split-bf16 mainloop: acc[4][4][4] += A[row0:+128, :1024] @ B[col0:+128, :1024]^T
// A,B row-major [*,1024]. 8 warps: warp (wm=wid>>2, wn=wid&3) owns 64x32.
// ------------------------------------------------------------------
__device__ __forceinline__ void bf16_mainloop(
    const float* __restrict__ A, const float* __restrict__ Bm,
    int row0, int col0, unsigned* u, float acc[4][4][4])
{
    const int tid = threadIdx.x;
    const int wid = tid >> 5, lane = tid & 31;
    const int wm = wid >> 2, wn = wid & 3;
    const int grp = lane >> 2, qid = lane & 3;

    // per-thread fill coordinates (4 float4 each for A and B)
    const float* aP[4]; const float* bP[4];
    int stOff[4];
    #pragma unroll
    for (int v = 0; v < 4; v++) {
        int q = tid + 256 * v;
        int r = q >> 3, kq = (q & 7) << 2;
        aP[v] = A  + (size_t)(row0 + r) * DIM_ + kq;
        bP[v] = Bm + (size_t)(col0 + r) * DIM_ + kq;
        stOff[v] = r * 20 + (kq >> 1);
    }

    float4 pA[4], pB[4];
    #pragma unroll
    for (int v = 0; v < 4; v++) { pA[v] = *(const float4*)aP[v]; pB[v] = *(const float4*)bP[v]; }

    for (int c = 0; c < 32; c++) {
        unsigned* st = u + (c & 1) * SWRD;
        #pragma unroll
        for (int v = 0; v < 4; v++) {
            unsigned h0, l0, h1, l1;
            split2(pA[v].x, pA[v].y, h0, l0);
            split2(pA[v].z, pA[v].w, h1, l1);
            st[stOff[v]] = h0; st[stOff[v] + 1] = h1;
            st[O_ALO + stOff[v]] = l0; st[O_ALO + stOff[v] + 1] = l1;
            split2(pB[v].x, pB[v].y, h0, l0);
            split2(pB[v].z, pB[v].w, h1, l1);
            st[O_BHI + stOff[v]] = h0; st[O_BHI + stOff[v] + 1] = h1;
            st[O_BLO + stOff[v]] = l0; st[O_BLO + stOff[v] + 1] = l1;
        }
        __syncthreads();
        if (c < 31) {
            #pragma unroll
            for (int v = 0; v < 4; v++) {
                pA[v] = *(const float4*)(aP[v] + (c + 1) * 32);
                pB[v] = *(const float4*)(bP[v] + (c + 1) * 32);
            }
        }
        const unsigned* Ah = u + (c & 1) * SWRD;
        const unsigned* Al = Ah + O_ALO;
        const unsigned* Bh = Ah + O_BHI;
        const unsigned* Bl = Ah + O_BLO;

        #pragma unroll
        for (int ks = 0; ks < 2; ks++) {
            const int wb = 8 * ks + qid;
            unsigned bh[4][2], bl[4][2];
            #pragma unroll
            for (int ni = 0; ni < 4; ni++) {
                int nr = (32 * wn + 8 * ni + grp) * 20;
                bh[ni][0] = Bh[nr + wb]; bh[ni][1] = Bh[nr + wb + 4];
                bl[ni][0] = Bl[nr + wb]; bl[ni][1] = Bl[nr + wb + 4];
            }
            #pragma unroll
            for (int mi = 0; mi < 4; mi++) {
                int ar0 = (64 * wm + 16 * mi + grp) * 20;
                int ar1 = ar0 + 8 * 20;
                unsigned ah0 = Ah[ar0 + wb],     ah1 = Ah[ar1 + wb];
                unsigned ah2 = Ah[ar0 + wb + 4], ah3 = Ah[ar1 + wb + 4];
                unsigned al0 = Al[ar0 + wb],     al1 = Al[ar1 + wb];
                unsigned al2 = Al[ar0 + wb + 4], al3 = Al[ar1 + wb + 4];
                #pragma unroll
                for (int ni = 0; ni < 4; ni++) {
                    mma16816(acc[mi][ni], ah0, ah1, ah2, ah3, bh[ni][0], bh[ni][1]);
                    mma16816(acc[mi][ni], ah0, ah1, ah2, ah3, bl[ni][0], bl[ni][1]);
                    mma16816(acc[mi][ni], al0, al1, al2, al3, bh[ni][0], bh[ni][1]);
                }
            }
        }
    }
    __syncthreads();  // tiles idle before epilogue reuses the space
}

// ------------------------------------------------------------------
// Kernel 1: QKV GEMM + fused per-head LayerNorm + RoPE.
// Grid (24, 32): col tile = 2 heads of one of q/k/v.
// ------------------------------------------------------------------
__global__ __launch_bounds__(256) void qkv_mm(
    const float* __restrict__ x, const float* __restrict__ w,
    const float* __restrict__ qn_w, const float* __restrict__ qn_b,
    const float* __restrict__ kn_w, const float* __restrict__ kn_b)
{
    extern __shared__ __align__(16) unsigned u[];
    const int tid = threadIdx.x;
    const int wid = tid >> 5, lane = tid & 31;
    const int wm = wid >> 2, wn = wid & 3;
    const int grp = lane >> 2, qid = lane & 3;
    const int row0 = blockIdx.y * 128;
    const int col0 = blockIdx.x * 128;

    float acc[4][4][4];
    #pragma unroll
    for (int i = 0; i < 4; i++)
        #pragma unroll
        for (int j = 0; j < 4; j++)
            #pragma unroll
            for (int k = 0; k < 4; k++) acc[i][j][k] = 0.f;

    bf16_mainloop(x, w, row0, col0, u, acc);

    // stage 128x128 f32 tile (stride 132)
    float* stg = (float*)u;
    #pragma unroll
    for (int mi = 0; mi < 4; mi++) {
        int rr = 64 * wm + 16 * mi + grp;
        #pragma unroll
        for (int ni = 0; ni < 4; ni++) {
            int cc = 32 * wn + 8 * ni + 2 * qid;
            stg[rr * 132 + cc]           = acc[mi][ni][0];
            stg[rr * 132 + cc + 1]       = acc[mi][ni][1];
            stg[(rr + 8) * 132 + cc]     = acc[mi][ni][2];
            stg[(rr + 8) * 132 + cc + 1] = acc[mi][ni][3];
        }
    }
    __syncthreads();

    const int hh = tid >> 7, r = tid & 127;
    float d[64];
    const float* src = stg + r * 132 + hh * 64;
    #pragma unroll
    for (int j = 0; j < 16; j++) {
        float4 v = *(const float4*)(src + 4 * j);
        d[4*j] = v.x; d[4*j+1] = v.y; d[4*j+2] = v.z; d[4*j+3] = v.w;
    }

    const int t = col0 >> 10;
    const int h = ((col0 & 1023) >> 6) + hh;
    const int grow = row0 + r;
    const int b = grow >> 10, n = grow & 1023;

    float* dst;
    if (t == 2) {
        dst = g_V;
    } else {
        const float* lw = t ? kn_w : qn_w;
        const float* lb = t ? kn_b : qn_b;
        float s1 = 0.f, s2 = 0.f;
        #pragma unroll
        for (int j = 0; j < 64; j++) { s1 += d[j]; s2 += d[j] * d[j]; }
        float mu = s1 * (1.f / 64.f);
        float var = s2 * (1.f / 64.f) - mu * mu;
        float rstd = rsqrtf(var + 1e-5f);
        #pragma unroll
        for (int j = 0; j < 64; j++)
            d[j] = (d[j] - mu) * rstd * __ldg(lw + j) + __ldg(lb + j);
        #pragma unroll
        for (int j = 0; j < 32; j++) {
            float invf = expf(-(float)j * 0.2878231366242557f);  // 10000^(-j/32)
            float sn, cs;
            sincosf((float)n * invf, &sn, &cs);
            float t0 = d[j];
            d[j]      = t0 * cs - d[j + 32] * sn;
            d[j + 32] = d[j + 32] * cs + t0 * sn;
        }
        dst = t ? g_K : g_Q;
    }
    float* o = dst + ((size_t)(b * H_ + h) * N_ + n) * D_;
    #pragma unroll
    for (int j = 0; j < 16; j++)
        *(float4*)(o + 4 * j) = make_float4(d[4*j], d[4*j+1], d[4*j+2], d[4*j+3]);
}

// ------------------------------------------------------------------
// Kernel 3: output projection GEMM + bias. Grid (8, 32).
// ------------------------------------------------------------------
__global__ __launch_bounds__(256) void proj_mm(
    const float* __restrict__ w, const float* __restrict__ bias,
    float* __restrict__ out)
{
    extern __shared__ __align__(16) unsigned u[];
    const int tid = threadIdx.x;
    const int wid = tid >> 5, lane = tid & 31;
    const int wm = wid >> 2, wn = wid & 3;
    const int grp = lane >> 2, qid = lane & 3;
    const int row0 = blockIdx.y * 128;
    const int col0 = blockIdx.x * 128;

    float acc[4][4][4];
    #pragma unroll
    for (int i = 0; i < 4; i++)
        #pragma unroll
        for (int j = 0; j < 4; j++)
            #pragma unroll
            for (int k = 0; k < 4; k++) acc[i][j][k] = 0.f;

    bf16_mainloop(g_AO, w, row0, col0, u, acc);

    #pragma unroll
    for (int mi = 0; mi < 4; mi++) {
        int rr = row0 + 64 * wm + 16 * mi + grp;
        #pragma unroll
        for (int ni = 0; ni < 4; ni++) {
            int cc = col0 + 32 * wn + 8 * ni + 2 * qid;
            float b0 = __ldg(bias + cc), b1 = __ldg(bias + cc + 1);
            *(float2*)(out + (size_t)rr * DIM_ + cc) =
                make_float2(acc[mi][ni][0] + b0, acc[mi][ni][1] + b1);
            *(float2*)(out + (size_t)(rr + 8) * DIM_ + cc) =
                make_float2(acc[mi][ni][2] + b0, acc[mi][ni][3] + b1);
        }
    }
}

// ------------------------------------------------------------------
// Kernel 2: sliding-window attention with sink (fp32 SIMT, R1-verified).
// ------------------------------------------------------------------
__global__ __launch_bounds__(256) void attn_kernel(const float* __restrict__ sinks)
{
    __shared__ __align__(16) float Qs[64][64];
    __shared__ __align__(16) float KP[64][64];
    __shared__ __align__(16) float Vs[64][64];

    const int bh = blockIdx.y;
    const int b = bh >> 4, h = bh & 15;
    const int q0 = blockIdx.x * 64;
    const int tid = threadIdx.x;
    const int tx = tid & 15, ty = tid >> 4;

    const float* Qg = g_Q + (size_t)((b * H_ + h) * N_) * D_;
    const float* Kg = g_K + (size_t)((b * H_ + h) * N_) * D_;
    const float* Vg = g_V + (size_t)((b * H_ + h) * N_) * D_;

    #pragma unroll
    for (int v = 0; v < 4; v++) {
        int idx = tid + v * 256;
        int r = idx >> 4, c = (idx & 15) << 2;
        float4 qv = *(const float4*)(Qg + (size_t)(q0 + r) * D_ + c);
        Qs[c + 0][r] = qv.x; Qs[c + 1][r] = qv.y;
        Qs[c + 2][r] = qv.z; Qs[c + 3][r] = qv.w;
    }

    const float snk = sinks[h];
    float m[4], dacc[4], o[4][4];
    #pragma unroll
    for (int i = 0; i < 4; i++) {
        m[i] = snk; dacc[i] = 1.f;
        #pragma unroll
        for (int j = 0; j < 4; j++) o[i][j] = 0.f;
    }

    const int kt_lo = (q0 >= SW_) ? ((q0 - SW_ + 1) >> 6) : 0;
    const int kt_hi = q0 >> 6;

    for (int kt = kt_lo; kt <= kt_hi; kt++) {
        const int k0 = kt << 6;
        __syncthreads();
        #pragma unroll
        for (int v = 0; v < 4; v++) {
            int idx = tid + v * 256;
            int r = idx >> 4, c = (idx & 15) << 2;
            float4 kv = *(const float4*)(Kg + (size_t)(k0 + r) * D_ + c);
            KP[c + 0][r] = kv.x; KP[c + 1][r] = kv.y;
            KP[c + 2][r] = kv.z; KP[c + 3][r] = kv.w;
            float4 vv = *(const float4*)(Vg + (size_t)(k0 + r) * D_ + c);
            *(float4*)&Vs[r][c] = vv;
        }
        __syncthreads();

        float s[4][4];
        #pragma unroll
        for (int i = 0; i < 4; i++)
            #pragma unroll
            for (int j = 0; j < 4; j++) s[i][j] = 0.f;

        #pragma unroll 8
        for (int kk = 0; kk < 64; kk++) {
            float4 qf = *(float4*)&Qs[kk][ty * 4];
            float4 kf = *(float4*)&KP[kk][tx * 4];
            float qa[4] = {qf.x, qf.y, qf.z, qf.w};
            float ka[4] = {kf.x, kf.y, kf.z, kf.w};
            #pragma unroll
            for (int i = 0; i < 4; i++)
                #pragma unroll
                for (int j = 0; j < 4; j++)
                    s[i][j] = fmaf(qa[i], ka[j], s[i][j]);
        }

        #pragma unroll
        for (int i = 0; i < 4; i++) {
            int gi = q0 + ty * 4 + i;
            #pragma unroll
            for (int j = 0; j < 4; j++) {
                int gj = k0 + tx * 4 + j;
                bool ok = (gj <= gi) && (gj > gi - SW_);
                s[i][j] = ok ? s[i][j] * 0.125f : -1e30f;
            }
            float rm = fmaxf(fmaxf(s[i][0], s[i][1]), fmaxf(s[i][2], s[i][3]));
            #pragma unroll
            for (int off = 1; off < 16; off <<= 1)
                rm = fmaxf(rm, __shfl_xor_sync(0xffffffffu, rm, off));
            float mn = fmaxf(m[i], rm);
            float sc = __expf(m[i] - mn);
            m[i] = mn; dacc[i] *= sc;
            #pragma unroll
            for (int j = 0; j < 4; j++) o[i][j] *= sc;
            float rs = 0.f;
            #pragma unroll
            for (int j = 0; j < 4; j++) {
                s[i][j] = __expf(s[i][j] - mn);
                rs += s[i][j];
            }
            #pragma unroll
            for (int off = 1; off < 16; off <<= 1)
                rs += __shfl_xor_sync(0xffffffffu, rs, off);
            dacc[i] += rs;
        }

        __syncthreads();
        #pragma unroll
        for (int i = 0; i < 4; i++)
            *(float4*)&KP[ty * 4 + i][tx * 4] =
                make_float4(s[i][0], s[i][1], s[i][2], s[i][3]);
        __syncthreads();

        #pragma unroll 4
        for (int j0 = 0; j0 < 64; j0 += 4) {
            float4 vv0 = *(float4*)&Vs[j0 + 0][tx * 4];
            float4 vv1 = *(float4*)&Vs[j0 + 1][tx * 4];
            float4 vv2 = *(float4*)&Vs[j0 + 2][tx * 4];
            float4 vv3 = *(float4*)&Vs[j0 + 3][tx * 4];
            #pragma unroll
            for (int i = 0; i < 4; i++) {
                float4 pv = *(float4*)&KP[ty * 4 + i][j0];
                o[i][0] = fmaf(pv.x, vv0.x, fmaf(pv.y, vv1.x, fmaf(pv.z, vv2.x, fmaf(pv.w, vv3.x, o[i][0]))));
                o[i][1] = fmaf(pv.x, vv0.y, fmaf(pv.y, vv1.y, fmaf(pv.z, vv2.y, fmaf(pv.w, vv3.y, o[i][1]))));
                o[i][2] = fmaf(pv.x, vv0.z, fmaf(pv.y, vv1.z, fmaf(pv.z, vv2.z, fmaf(pv.w, vv3.z, o[i][2]))));
                o[i][3] = fmaf(pv.x, vv0.w, fmaf(pv.y, vv1.w, fmaf(pv.z, vv2.w, fmaf(pv.w, vv3.w, o[i][3]))));
            }
        }
    }

    #pragma unroll
    for (int i = 0; i < 4; i++) {
        float inv = 1.f / dacc[i];
        int gi = q0 + ty * 4 + i;
        *(float4*)(g_AO + (size_t)((b * N_ + gi) * H_ + h) * D_ + tx * 4) =
            make_float4(o[i][0] * inv, o[i][1] * inv, o[i][2] * inv, o[i][3] * inv);
    }
}

extern "C" void kernel_launch(void* const* d_in, const int* in_sizes, int n_in,
                              void* d_out, int out_size)
{
    const float* x      = (const float*)d_in[0];
    const float* qkv_w  = (const float*)d_in[1];
    const float* qn_w   = (const float*)d_in[2];
    const float* qn_b   = (const float*)d_in[3];
    const float* kn_w   = (const float*)d_in[4];
    const float* kn_b   = (const float*)d_in[5];
    const float* sinks  = (const float*)d_in[6];
    const float* proj_w = (const float*)d_in[7];
    const float* proj_b = (const float*)d_in[8];
    float* out = (float*)d_out;

    static bool attr_set = false;
    if (!attr_set) {
        cudaFuncSetAttribute(qkv_mm,  cudaFuncAttributeMaxDynamicSharedMemorySize, GEMM_SMEM);
        cudaFuncSetAttribute(proj_mm, cudaFuncAttributeMaxDynamicSharedMemorySize, GEMM_SMEM);
        attr_set = true;
    }

    qkv_mm<<<dim3(24, 32), 256, GEMM_SMEM>>>(x, qkv_w, qn_w, qn_b, kn_w, kn_b);
    attn_kernel<<<dim3(16, 64), 256>>>(sinks);
    proj_mm<<<dim3(8, 32), 256, GEMM_SMEM>>>(proj_w, proj_b, out);
}

// round 4
// speedup vs baseline: 2.6270x; 1.3387x over previous
#include <cuda_runtime.h>
#include <cuda_bf16.h>
#include <cuda_fp16.h>
#include <math.h>
#include <cstdint>

#define B_   4
#define N_   1024
#define DIM_ 1024
#define H_   16
#define D_   64
#define SW_  256
#define LOG2E  1.4426950408889634f
#define QSCALE 0.18033688011112042f   // sm_scale * log2(e)

// ---------------- device globals (word = 2 bf16/f16) ----------------
__device__ unsigned g_xh[2097152],  g_xl[2097152];    // x      4096x1024 bf16
__device__ unsigned g_wh[1572864],  g_wl[1572864];    // qkv_w  3072x1024 bf16
__device__ unsigned g_pwh[524288],  g_pwl[524288];    // proj_w 1024x1024 bf16
__device__ unsigned g_Qh[2097152],  g_Ql[2097152];    // [b,h,n,d] bf16 (pre-scaled)
__device__ unsigned g_Kh[2097152],  g_Kl[2097152];    // [b,h,n,d] bf16
__device__ unsigned g_Vh[2097152],  g_Vl[2097152];    // [b,h,n,d] f16
__device__ unsigned g_AOh[2097152], g_AOl[2097152];   // [b*n, h*d] bf16

// ---------------- helpers ----------------
__device__ __forceinline__ void split2(float x, float y, unsigned &hi, unsigned &lo) {
    __nv_bfloat16 hx = __float2bfloat16(x), hy = __float2bfloat16(y);
    float rx = x - __bfloat162float(hx);
    float ry = y - __bfloat162float(hy);
    __nv_bfloat16 lx = __float2bfloat16(rx), ly = __float2bfloat16(ry);
    hi = ((unsigned)__bfloat16_as_ushort(hy) << 16) | (unsigned)__bfloat16_as_ushort(hx);
    lo = ((unsigned)__bfloat16_as_ushort(ly) << 16) | (unsigned)__bfloat16_as_ushort(lx);
}
__device__ __forceinline__ void splitf16(float x, float y, unsigned &hi, unsigned &lo) {
    __half hx = __float2half_rn(x), hy = __float2half_rn(y);
    float rx = x - __half2float(hx);
    float ry = y - __half2float(hy);
    __half lx = __float2half_rn(rx), ly = __float2half_rn(ry);
    hi = ((unsigned)__half_as_ushort(hy) << 16) | (unsigned)__half_as_ushort(hx);
    lo = ((unsigned)__half_as_ushort(ly) << 16) | (unsigned)__half_as_ushort(lx);
}
__device__ __forceinline__ void mma16816(float* c, unsigned a0, unsigned a1,
                                         unsigned a2, unsigned a3,
                                         unsigned b0, unsigned b1) {
    asm volatile(
        "mma.sync.aligned.m16n8k16.row.col.f32.bf16.bf16.f32 "
        "{%0,%1,%2,%3}, {%4,%5,%6,%7}, {%8,%9}, {%0,%1,%2,%3};"
        : "+f"(c[0]), "+f"(c[1]), "+f"(c[2]), "+f"(c[3])
        : "r"(a0), "r"(a1), "r"(a2), "r"(a3), "r"(b0), "r"(b1));
}
__device__ __forceinline__ void mma16816h(float* c, unsigned a0, unsigned a1,
                                          unsigned a2, unsigned a3,
                                          unsigned b0, unsigned b1) {
    asm volatile(
        "mma.sync.aligned.m16n8k16.row.col.f32.f16.f16.f32 "
        "{%0,%1,%2,%3}, {%4,%5,%6,%7}, {%8,%9}, {%0,%1,%2,%3};"
        : "+f"(c[0]), "+f"(c[1]), "+f"(c[2]), "+f"(c[3])
        : "r"(a0), "r"(a1), "r"(a2), "r"(a3), "r"(b0), "r"(b1));
}
__device__ __forceinline__ float ex2f(float x) {
    float y; asm("ex2.approx.f32 %0, %1;" : "=f"(y) : "f"(x)); return y;
}
__device__ __forceinline__ unsigned smem_u32(const void* p){
    unsigned a;
    asm("{ .reg .u64 t; cvta.to.shared.u64 t, %1; cvt.u32.u64 %0, t; }" : "=r"(a) : "l"(p));
    return a;
}
__device__ __forceinline__ void cpa16(unsigned daddr, const void* g){
    asm volatile("cp.async.ca.shared.global [%0], [%1], 16;" :: "r"(daddr), "l"(g) : "memory");
}
#define CP_COMMIT() asm volatile("cp.async.commit_group;" ::: "memory")

// ---------------- presplit: fp32 -> bf16 hi/lo ----------------
__global__ void presplit_all(const float4* __restrict__ x,
                             const float4* __restrict__ w,
                             const float4* __restrict__ pw)
{
    const float4* s; uint2 *hp, *lp; int n4;
    if (blockIdx.y == 0)      { s = x;  hp = (uint2*)g_xh;  lp = (uint2*)g_xl;  n4 = 1048576; }
    else if (blockIdx.y == 1) { s = w;  hp = (uint2*)g_wh;  lp = (uint2*)g_wl;  n4 = 786432; }
    else                      { s = pw; hp = (uint2*)g_pwh; lp = (uint2*)g_pwl; n4 = 262144; }
    for (int i = blockIdx.x * blockDim.x + threadIdx.x; i < n4; i += gridDim.x * blockDim.x) {
        float4 f = s[i];
        unsigned h0, l0, h1, l1;
        split2(f.x, f.y, h0, l0);
        split2(f.z, f.w, h1, l1);
        hp[i] = make_uint2(h0, h1);
        lp[i] = make_uint2(l0, l1);
    }
}

// ---------------- GEMM mainloop (pre-split operands, cp.async) ----------------
// smem stage (words): Ah@0, Al@2560, Bh@5120, Bl@7680; row stride 20 words.
#define SWRD   10240
#define O_ALO  2560
#define O_BHI  5120
#define O_BLO  7680
#define GEMM_SMEM 81920

__device__ __forceinline__ void mainloop_pre(
    const unsigned* __restrict__ gAh, const unsigned* __restrict__ gAl,
    const unsigned* __restrict__ gBh, const unsigned* __restrict__ gBl,
    int row0, int col0, unsigned* u, float acc[4][4][4])
{
    const int tid = threadIdx.x;
    const int wid = tid >> 5, lane = tid & 31;
    const int wm = wid >> 2, wn = wid & 3;
    const int grp = lane >> 2, qid = lane & 3;
    const unsigned ub = smem_u32(u);

    int rr[2], kk[2], dof[2];
    #pragma unroll
    for (int v = 0; v < 2; v++) {
        int q = tid + 256 * v;         // 0..511 (512 float4 per array per chunk)
        rr[v] = q >> 2;
        kk[v] = (q & 3) << 2;
        dof[v] = rr[v] * 20 + kk[v];
    }
    const unsigned* aH = gAh + (size_t)row0 * 512;
    const unsigned* aL = gAl + (size_t)row0 * 512;
    const unsigned* bH = gBh + (size_t)col0 * 512;
    const unsigned* bL = gBl + (size_t)col0 * 512;

    // fill chunk 0 into stage 0
    #pragma unroll
    for (int v = 0; v < 2; v++) {
        int so = rr[v] * 512 + kk[v];
        unsigned da = ub + (unsigned)(dof[v] << 2);
        cpa16(da,               aH + so);
        cpa16(da + O_ALO * 4,   aL + so);
        cpa16(da + O_BHI * 4,   bH + so);
        cpa16(da + O_BLO * 4,   bL + so);
    }
    CP_COMMIT();

    for (int c = 0; c < 32; c++) {
        if (c < 31) {
            const int s1 = (c + 1) & 1;
            #pragma unroll
            for (int v = 0; v < 2; v++) {
                int so = rr[v] * 512 + (c + 1) * 16 + kk[v];
                unsigned da = ub + (unsigned)((s1 * SWRD + dof[v]) << 2);
                cpa16(da,               aH + so);
                cpa16(da + O_ALO * 4,   aL + so);
                cpa16(da + O_BHI * 4,   bH + so);
                cpa16(da + O_BLO * 4,   bL + so);
            }
            CP_COMMIT();
            asm volatile("cp.async.wait_group 1;" ::: "memory");
        } else {
            asm volatile("cp.async.wait_group 0;" ::: "memory");
        }
        __syncthreads();

        const unsigned* Ahs = u + (c & 1) * SWRD;
        const unsigned* Als = Ahs + O_ALO;
        const unsigned* Bhs = Ahs + O_BHI;
        const unsigned* Bls = Ahs + O_BLO;

        #pragma unroll
        for (int ks = 0; ks < 2; ks++) {
            const int wb = 8 * ks + qid;
            unsigned bh[4][2], bl[4][2];
            #pragma unroll
            for (int ni = 0; ni < 4; ni++) {
                int nr = (32 * wn + 8 * ni + grp) * 20;
                bh[ni][0] = Bhs[nr + wb]; bh[ni][1] = Bhs[nr + wb + 4];
                bl[ni][0] = Bls[nr + wb]; bl[ni][1] = Bls[nr + wb + 4];
            }
            #pragma unroll
            for (int mi = 0; mi < 4; mi++) {
                int ar0 = (64 * wm + 16 * mi + grp) * 20;
                int ar1 = ar0 + 8 * 20;
                unsigned ah0 = Ahs[ar0 + wb],     ah1 = Ahs[ar1 + wb];
                unsigned ah2 = Ahs[ar0 + wb + 4], ah3 = Ahs[ar1 + wb + 4];
                unsigned al0 = Als[ar0 + wb],     al1 = Als[ar1 + wb];
                unsigned al2 = Als[ar0 + wb + 4], al3 = Als[ar1 + wb + 4];
                #pragma unroll
                for (int ni = 0; ni < 4; ni++) {
                    mma16816(acc[mi][ni], ah0, ah1, ah2, ah3, bh[ni][0], bh[ni][1]);
                    mma16816(acc[mi][ni], ah0, ah1, ah2, ah3, bl[ni][0], bl[ni][1]);
                    mma16816(acc[mi][ni], al0, al1, al2, al3, bh[ni][0], bh[ni][1]);
                }
            }
        }
        __syncthreads();
    }
}

// ---------------- Kernel 1: QKV GEMM + LN + RoPE + split-store ----------------
__global__ __launch_bounds__(256, 2) void qkv_mm(
    const float* __restrict__ qn_w, const float* __restrict__ qn_b,
    const float* __restrict__ kn_w, const float* __restrict__ kn_b)
{
    extern __shared__ __align__(16) unsigned u[];
    const int tid = threadIdx.x;
    const int wid = tid >> 5, lane = tid & 31;
    const int wm = wid >> 2, wn = wid & 3;
    const int grp = lane >> 2, qid = lane & 3;
    const int row0 = blockIdx.y * 128;
    const int col0 = blockIdx.x * 128;

    float acc[4][4][4];
    #pragma unroll
    for (int i = 0; i < 4; i++)
        #pragma unroll
        for (int j = 0; j < 4; j++)
            #pragma unroll
            for (int k = 0; k < 4; k++) acc[i][j][k] = 0.f;

    mainloop_pre(g_xh, g_xl, g_wh, g_wl, row0, col0, u, acc);

    // stage 128x128 f32 tile (stride 132)
    float* stg = (float*)u;
    #pragma unroll
    for (int mi = 0; mi < 4; mi++) {
        int rr2 = 64 * wm + 16 * mi + grp;
        #pragma unroll
        for (int ni = 0; ni < 4; ni++) {
            int cc = 32 * wn + 8 * ni + 2 * qid;
            stg[rr2 * 132 + cc]           = acc[mi][ni][0];
            stg[rr2 * 132 + cc + 1]       = acc[mi][ni][1];
            stg[(rr2 + 8) * 132 + cc]     = acc[mi][ni][2];
            stg[(rr2 + 8) * 132 + cc + 1] = acc[mi][ni][3];
        }
    }
    __syncthreads();

    const int hh = tid >> 7, r = tid & 127;
    float d[64];
    const float* src = stg + r * 132 + hh * 64;
    #pragma unroll
    for (int j = 0; j < 16; j++) {
        float4 v = *(const float4*)(src + 4 * j);
        d[4*j] = v.x; d[4*j+1] = v.y; d[4*j+2] = v.z; d[4*j+3] = v.w;
    }

    const int t = col0 >> 10;                      // 0=q,1=k,2=v
    const int h = ((col0 & 1023) >> 6) + hh;
    const int grow = row0 + r;
    const int b = grow >> 10, n = grow & 1023;
    const size_t wbase = ((size_t)(b * H_ + h) * N_ + n) * 32;   // word offset

    unsigned hw[32], lw2[32];
    if (t == 2) {
        #pragma unroll
        for (int cpair = 0; cpair < 32; cpair++)
            splitf16(d[2*cpair], d[2*cpair+1], hw[cpair], lw2[cpair]);
        #pragma unroll
        for (int q8 = 0; q8 < 8; q8++) {
            *(uint4*)(g_Vh + wbase + 4*q8) = make_uint4(hw[4*q8], hw[4*q8+1], hw[4*q8+2], hw[4*q8+3]);
            *(uint4*)(g_Vl + wbase + 4*q8) = make_uint4(lw2[4*q8], lw2[4*q8+1], lw2[4*q8+2], lw2[4*q8+3]);
        }
        return;
    }

    const float* lw = t ? kn_w : qn_w;
    const float* lb = t ? kn_b : qn_b;
    float s1 = 0.f, s2 = 0.f;
    #pragma unroll
    for (int j = 0; j < 64; j++) { s1 += d[j]; s2 += d[j] * d[j]; }
    float mu = s1 * (1.f / 64.f);
    float var = s2 * (1.f / 64.f) - mu * mu;
    float rstd = rsqrtf(var + 1e-5f);
    #pragma unroll
    for (int j = 0; j < 64; j++)
        d[j] = (d[j] - mu) * rstd * __ldg(lw + j) + __ldg(lb + j);
    #pragma unroll
    for (int j = 0; j < 32; j++) {
        float invf = expf(-(float)j * 0.2878231366242557f);   // 10000^(-j/32)
        float sn, cs;
        sincosf((float)n * invf, &sn, &cs);
        float t0 = d[j];
        d[j]      = t0 * cs - d[j + 32] * sn;
        d[j + 32] = d[j + 32] * cs + t0 * sn;
    }
    if (t == 0) {
        #pragma unroll
        for (int j = 0; j < 64; j++) d[j] *= QSCALE;           // fold sm_scale*log2e into Q
    }
    #pragma unroll
    for (int cpair = 0; cpair < 32; cpair++)
        split2(d[2*cpair], d[2*cpair+1], hw[cpair], lw2[cpair]);
    unsigned* dh = t ? g_Kh : g_Qh;
    unsigned* dl = t ? g_Kl : g_Ql;
    #pragma unroll
    for (int q8 = 0; q8 < 8; q8++) {
        *(uint4*)(dh + wbase + 4*q8) = make_uint4(hw[4*q8], hw[4*q8+1], hw[4*q8+2], hw[4*q8+3]);
        *(uint4*)(dl + wbase + 4*q8) = make_uint4(lw2[4*q8], lw2[4*q8+1], lw2[4*q8+2], lw2[4*q8+3]);
    }
}

// ---------------- Kernel 3: proj GEMM + bias ----------------
__global__ __launch_bounds__(256, 2) void proj_mm(
    const float* __restrict__ bias, float* __restrict__ out)
{
    extern __shared__ __align__(16) unsigned u[];
    const int tid = threadIdx.x;
    const int wid = tid >> 5, lane = tid & 31;
    const int wm = wid >> 2, wn = wid & 3;
    const int grp = lane >> 2, qid = lane & 3;
    const int row0 = blockIdx.y * 128;
    const int col0 = blockIdx.x * 128;

    float acc[4][4][4];
    #pragma unroll
    for (int i = 0; i < 4; i++)
        #pragma unroll
        for (int j = 0; j < 4; j++)
            #pragma unroll
            for (int k = 0; k < 4; k++) acc[i][j][k] = 0.f;

    mainloop_pre(g_AOh, g_AOl, g_pwh, g_pwl, row0, col0, u, acc);

    #pragma unroll
    for (int mi = 0; mi < 4; mi++) {
        int rr = row0 + 64 * wm + 16 * mi + grp;
        #pragma unroll
        for (int ni = 0; ni < 4; ni++) {
            int cc = col0 + 32 * wn + 8 * ni + 2 * qid;
            float b0 = __ldg(bias + cc), b1 = __ldg(bias + cc + 1);
            *(float2*)(out + (size_t)rr * DIM_ + cc) =
                make_float2(acc[mi][ni][0] + b0, acc[mi][ni][1] + b1);
            *(float2*)(out + (size_t)(rr + 8) * DIM_ + cc) =
                make_float2(acc[mi][ni][2] + b0, acc[mi][ni][3] + b1);
        }
    }
}

// ---------------- Kernel 2: tensor-core flash attention ----------------
// smem word offsets: Qh,Ql,Kh,Kl,Vth,Vtl each 64 rows x 36 words
#define AQH 0
#define AQL 2304
#define AKH 4608
#define AKL 6912
#define AVH 9216
#define AVL 11520
#define ATT_SMEM 55296

__global__ __launch_bounds__(128) void attn_tc(const float* __restrict__ sinks)
{
    extern __shared__ __align__(16) unsigned u[];
    const int tid = threadIdx.x;
    const int wid = tid >> 5, lane = tid & 31;
    const int grp = lane >> 4 ? 0 : 0; // placeholder
    const int g8 = lane >> 2, qid = lane & 3;
    const int bh = blockIdx.y, b = bh >> 4, h = bh & 15;
    const int q0 = blockIdx.x * 64;

    const size_t base = (size_t)(b * H_ + h) * N_ * 32;   // word base of this (b,h)
    const unsigned* Qhg = g_Qh + base + (size_t)q0 * 32;
    const unsigned* Qlg = g_Ql + base + (size_t)q0 * 32;
    const unsigned* Khg = g_Kh + base;
    const unsigned* Klg = g_Kl + base;
    const unsigned* Vhg = g_Vh + base;
    const unsigned* Vlg = g_Vl + base;

    #pragma unroll
    for (int v = 0; v < 4; v++) {
        int idx = tid + 128 * v;          // 0..511
        int r = idx >> 3, f = idx & 7;
        *(uint4*)(u + AQH + r * 36 + f * 4) = *(const uint4*)(Qhg + r * 32 + f * 4);
        *(uint4*)(u + AQL + r * 36 + f * 4) = *(const uint4*)(Qlg + r * 32 + f * 4);
    }

    float m0 = __ldg(sinks + h) * LOG2E, m1 = m0;
    float d0 = 1.f, d1 = 1.f;
    float oacc[8][4];
    #pragma unroll
    for (int i = 0; i < 8; i++)
        #pragma unroll
        for (int j = 0; j < 4; j++) oacc[i][j] = 0.f;

    const int i0 = q0 + 16 * wid + g8;
    const int i1 = i0 + 8;
    const int kt_lo = (q0 >= SW_) ? ((q0 - SW_ + 1) >> 6) : 0;
    const int kt_hi = q0 >> 6;

    for (int kt = kt_lo; kt <= kt_hi; kt++) {
        const int k0 = kt << 6;
        __syncthreads();
        unsigned short* VTH = (unsigned short*)(u + AVH);
        unsigned short* VTL = (unsigned short*)(u + AVL);
        #pragma unroll
        for (int v = 0; v < 4; v++) {
            int idx = tid + 128 * v;
            int r = idx >> 3, f = idx & 7;
            *(uint4*)(u + AKH + r * 36 + f * 4) = *(const uint4*)(Khg + (k0 + r) * 32 + f * 4);
            *(uint4*)(u + AKL + r * 36 + f * 4) = *(const uint4*)(Klg + (k0 + r) * 32 + f * 4);
            union { uint4 q; unsigned short s[8]; } tv, tl;
            tv.q = *(const uint4*)(Vhg + (k0 + r) * 32 + f * 4);
            tl.q = *(const uint4*)(Vlg + (k0 + r) * 32 + f * 4);
            #pragma unroll
            for (int e = 0; e < 8; e++) {
                VTH[(8 * f + e) * 72 + r] = tv.s[e];
                VTL[(8 * f + e) * 72 + r] = tl.s[e];
            }
        }
        __syncthreads();

        // S = Q K^T (bf16 3-pass, base-2 logits)
        float sacc[8][4];
        #pragma unroll
        for (int i = 0; i < 8; i++)
            #pragma unroll
            for (int j = 0; j < 4; j++) sacc[i][j] = 0.f;

        #pragma unroll
        for (int ks = 0; ks < 4; ks++) {
            const int wb = 8 * ks + qid;
            int ar0 = (16 * wid + g8) * 36 + wb, ar1 = ar0 + 8 * 36;
            unsigned ah0 = u[AQH + ar0], ah1 = u[AQH + ar1];
            unsigned ah2 = u[AQH + ar0 + 4], ah3 = u[AQH + ar1 + 4];
            unsigned al0 = u[AQL + ar0], al1 = u[AQL + ar1];
            unsigned al2 = u[AQL + ar0 + 4], al3 = u[AQL + ar1 + 4];
            #pragma unroll
            for (int ni = 0; ni < 8; ni++) {
                int nr = (8 * ni + g8) * 36 + wb;
                unsigned bh0 = u[AKH + nr], bh1 = u[AKH + nr + 4];
                unsigned bl0 = u[AKL + nr], bl1 = u[AKL + nr + 4];
                mma16816(sacc[ni], ah0, ah1, ah2, ah3, bh0, bh1);
                mma16816(sacc[ni], ah0, ah1, ah2, ah3, bl0, bl1);
                mma16816(sacc[ni], al0, al1, al2, al3, bh0, bh1);
            }
        }

        // mask + row max
        float mx0 = -1e30f, mx1 = -1e30f;
        #pragma unroll
        for (int ni = 0; ni < 8; ni++) {
            int j = k0 + 8 * ni + 2 * qid;
            sacc[ni][0] = (j     <= i0 && j     > i0 - SW_) ? sacc[ni][0] : -1e30f;
            sacc[ni][1] = (j + 1 <= i0 && j + 1 > i0 - SW_) ? sacc[ni][1] : -1e30f;
            sacc[ni][2] = (j     <= i1 && j     > i1 - SW_) ? sacc[ni][2] : -1e30f;
            sacc[ni][3] = (j + 1 <= i1 && j + 1 > i1 - SW_) ? sacc[ni][3] : -1e30f;
            mx0 = fmaxf(mx0, fmaxf(sacc[ni][0], sacc[ni][1]));
            mx1 = fmaxf(mx1, fmaxf(sacc[ni][2], sacc[ni][3]));
        }
        mx0 = fmaxf(mx0, __shfl_xor_sync(0xffffffffu, mx0, 1));
        mx0 = fmaxf(mx0, __shfl_xor_sync(0xffffffffu, mx0, 2));
        mx1 = fmaxf(mx1, __shfl_xor_sync(0xffffffffu, mx1, 1));
        mx1 = fmaxf(mx1, __shfl_xor_sync(0xffffffffu, mx1, 2));
        float mn0 = fmaxf(m0, mx0), mn1 = fmaxf(m1, mx1);
        float sc0 = ex2f(m0 - mn0), sc1 = ex2f(m1 - mn1);
        m0 = mn0; m1 = mn1; d0 *= sc0; d1 *= sc1;
        #pragma unroll
        for (int nd = 0; nd < 8; nd++) {
            oacc[nd][0] *= sc0; oacc[nd][1] *= sc0;
            oacc[nd][2] *= sc1; oacc[nd][3] *= sc1;
        }

        // e = 2^(s-m), split to f16 hi/lo; accumulate row sums
        unsigned pfh[8][2], pfl[8][2];
        float t0 = 0.f, t1 = 0.f;
        #pragma unroll
        for (int ni = 0; ni < 8; ni++) {
            float e0 = ex2f(fmaxf(sacc[ni][0] - mn0, -126.f));
            float e1 = ex2f(fmaxf(sacc[ni][1] - mn0, -126.f));
            float e2 = ex2f(fmaxf(sacc[ni][2] - mn1, -126.f));
            float e3 = ex2f(fmaxf(sacc[ni][3] - mn1, -126.f));
            t0 += e0 + e1; t1 += e2 + e3;
            splitf16(e0, e1, pfh[ni][0], pfl[ni][0]);
            splitf16(e2, e3, pfh[ni][1], pfl[ni][1]);
        }
        t0 += __shfl_xor_sync(0xffffffffu, t0, 1);
        t0 += __shfl_xor_sync(0xffffffffu, t0, 2);
        t1 += __shfl_xor_sync(0xffffffffu, t1, 1);
        t1 += __shfl_xor_sync(0xffffffffu, t1, 2);
        d0 += t0; d1 += t1;

        // O += P V (f16: Phi*Vhi + Phi*Vlo + Plo*Vhi)
        #pragma unroll
        for (int kf = 0; kf < 4; kf++) {
            unsigned a0 = pfh[2*kf][0], a1 = pfh[2*kf][1];
            unsigned a2 = pfh[2*kf+1][0], a3 = pfh[2*kf+1][1];
            unsigned c0 = pfl[2*kf][0], c1 = pfl[2*kf][1];
            unsigned c2 = pfl[2*kf+1][0], c3 = pfl[2*kf+1][1];
            const int wb = 8 * kf + qid;
            #pragma unroll
            for (int nd = 0; nd < 8; nd++) {
                int nr = (8 * nd + g8) * 36 + wb;
                unsigned vh0 = u[AVH + nr], vh1 = u[AVH + nr + 4];
                unsigned vl0 = u[AVL + nr], vl1 = u[AVL + nr + 4];
                mma16816h(oacc[nd], a0, a1, a2, a3, vh0, vh1);
                mma16816h(oacc[nd], a0, a1, a2, a3, vl0, vl1);
                mma16816h(oacc[nd], c0, c1, c2, c3, vh0, vh1);
            }
        }
    }

    // epilogue: AO[b*N + i, 64h + d] split bf16
    float inv0 = 1.f / d0, inv1 = 1.f / d1;
    #pragma unroll
    for (int nd = 0; nd < 8; nd++) {
        int col = 64 * h + 8 * nd + 2 * qid;
        unsigned hi, lo;
        split2(oacc[nd][0] * inv0, oacc[nd][1] * inv0, hi, lo);
        size_t w0 = ((size_t)(b * N_ + i0)) * 512 + (col >> 1);
        g_AOh[w0] = hi; g_AOl[w0] = lo;
        split2(oacc[nd][2] * inv1, oacc[nd][3] * inv1, hi, lo);
        size_t w1 = ((size_t)(b * N_ + i1)) * 512 + (col >> 1);
        g_AOh[w1] = hi; g_AOl[w1] = lo;
    }
}

extern "C" void kernel_launch(void* const* d_in, const int* in_sizes, int n_in,
                              void* d_out, int out_size)
{
    const float* x      = (const float*)d_in[0];
    const float* qkv_w  = (const float*)d_in[1];
    const float* qn_w   = (const float*)d_in[2];
    const float* qn_b   = (const float*)d_in[3];
    const float* kn_w   = (const float*)d_in[4];
    const float* kn_b   = (const float*)d_in[5];
    const float* sinks  = (const float*)d_in[6];
    const float* proj_w = (const float*)d_in[7];
    const float* proj_b = (const float*)d_in[8];
    float* out = (float*)d_out;

    cudaFuncSetAttribute(qkv_mm,  cudaFuncAttributeMaxDynamicSharedMemorySize, GEMM_SMEM);
    cudaFuncSetAttribute(proj_mm, cudaFuncAttributeMaxDynamicSharedMemorySize, GEMM_SMEM);
    cudaFuncSetAttribute(attn_tc, cudaFuncAttributeMaxDynamicSharedMemorySize, ATT_SMEM);

    presplit_all<<<dim3(1024, 3), 256>>>((const float4*)x, (const float4*)qkv_w,
                                         (const float4*)proj_w);
    qkv_mm<<<dim3(24, 32), 256, GEMM_SMEM>>>(qn_w, qn_b, kn_w, kn_b);
    attn_tc<<<dim3(16, 64), 128, ATT_SMEM>>>(sinks);
    proj_mm<<<dim3(8, 32), 256, GEMM_SMEM>>>(proj_b, out);
}

// round 5
// speedup vs baseline: 3.1836x; 1.2119x over previous
#include <cuda_runtime.h>
#include <cuda_bf16.h>
#include <cuda_fp16.h>
#include <math.h>
#include <cstdint>

#define B_   4
#define N_   1024
#define DIM_ 1024
#define H_   16
#define D_   64
#define SW_  256
#define LOG2E  1.4426950408889634f
#define QSCALE 0.18033688011112042f   // sm_scale * log2(e)

// ---------------- device globals (word = 2 bf16/f16) ----------------
__device__ unsigned g_xh[2097152],  g_xl[2097152];    // x      4096x1024 bf16
__device__ unsigned g_wh[1572864],  g_wl[1572864];    // qkv_w  3072x1024 bf16
__device__ unsigned g_pwh[524288],  g_pwl[524288];    // proj_w 1024x1024 bf16
__device__ unsigned g_Qh[2097152],  g_Ql[2097152];    // [b,h,n,d] bf16 (pre-scaled)
__device__ unsigned g_Kh[2097152],  g_Kl[2097152];    // [b,h,n,d] bf16
__device__ unsigned g_Vh[2097152],  g_Vl[2097152];    // [b,h,n,d] f16
__device__ unsigned g_AOh[2097152], g_AOl[2097152];   // [b*n, h*d] bf16

// ---------------- helpers ----------------
__device__ __forceinline__ void split2(float x, float y, unsigned &hi, unsigned &lo) {
    __nv_bfloat16 hx = __float2bfloat16(x), hy = __float2bfloat16(y);
    float rx = x - __bfloat162float(hx);
    float ry = y - __bfloat162float(hy);
    __nv_bfloat16 lx = __float2bfloat16(rx), ly = __float2bfloat16(ry);
    hi = ((unsigned)__bfloat16_as_ushort(hy) << 16) | (unsigned)__bfloat16_as_ushort(hx);
    lo = ((unsigned)__bfloat16_as_ushort(ly) << 16) | (unsigned)__bfloat16_as_ushort(lx);
}
__device__ __forceinline__ void splitf16(float x, float y, unsigned &hi, unsigned &lo) {
    __half hx = __float2half_rn(x), hy = __float2half_rn(y);
    float rx = x - __half2float(hx);
    float ry = y - __half2float(hy);
    __half lx = __float2half_rn(rx), ly = __float2half_rn(ry);
    hi = ((unsigned)__half_as_ushort(hy) << 16) | (unsigned)__half_as_ushort(hx);
    lo = ((unsigned)__half_as_ushort(ly) << 16) | (unsigned)__half_as_ushort(lx);
}
__device__ __forceinline__ void mma16816(float* c, unsigned a0, unsigned a1,
                                         unsigned a2, unsigned a3,
                                         unsigned b0, unsigned b1) {
    asm volatile(
        "mma.sync.aligned.m16n8k16.row.col.f32.bf16.bf16.f32 "
        "{%0,%1,%2,%3}, {%4,%5,%6,%7}, {%8,%9}, {%0,%1,%2,%3};"
        : "+f"(c[0]), "+f"(c[1]), "+f"(c[2]), "+f"(c[3])
        : "r"(a0), "r"(a1), "r"(a2), "r"(a3), "r"(b0), "r"(b1));
}
__device__ __forceinline__ void mma16816h(float* c, unsigned a0, unsigned a1,
                                          unsigned a2, unsigned a3,
                                          unsigned b0, unsigned b1) {
    asm volatile(
        "mma.sync.aligned.m16n8k16.row.col.f32.f16.f16.f32 "
        "{%0,%1,%2,%3}, {%4,%5,%6,%7}, {%8,%9}, {%0,%1,%2,%3};"
        : "+f"(c[0]), "+f"(c[1]), "+f"(c[2]), "+f"(c[3])
        : "r"(a0), "r"(a1), "r"(a2), "r"(a3), "r"(b0), "r"(b1));
}
__device__ __forceinline__ void ldsm4(unsigned &r0, unsigned &r1, unsigned &r2,
                                      unsigned &r3, unsigned addr) {
    asm volatile("ldmatrix.sync.aligned.m8n8.x4.shared.b16 {%0,%1,%2,%3}, [%4];"
                 : "=r"(r0), "=r"(r1), "=r"(r2), "=r"(r3) : "r"(addr));
}
__device__ __forceinline__ void ldsm4t(unsigned &r0, unsigned &r1, unsigned &r2,
                                       unsigned &r3, unsigned addr) {
    asm volatile("ldmatrix.sync.aligned.m8n8.x4.trans.shared.b16 {%0,%1,%2,%3}, [%4];"
                 : "=r"(r0), "=r"(r1), "=r"(r2), "=r"(r3) : "r"(addr));
}
__device__ __forceinline__ float ex2f(float x) {
    float y; asm("ex2.approx.f32 %0, %1;" : "=f"(y) : "f"(x)); return y;
}
__device__ __forceinline__ unsigned smem_u32(const void* p){
    unsigned a;
    asm("{ .reg .u64 t; cvta.to.shared.u64 t, %1; cvt.u32.u64 %0, t; }" : "=r"(a) : "l"(p));
    return a;
}
__device__ __forceinline__ void cpa16(unsigned daddr, const void* g){
    asm volatile("cp.async.ca.shared.global [%0], [%1], 16;" :: "r"(daddr), "l"(g) : "memory");
}
#define CP_COMMIT() asm volatile("cp.async.commit_group;" ::: "memory")

// ---------------- presplit: fp32 -> bf16 hi/lo ----------------
__global__ void presplit_all(const float4* __restrict__ x,
                             const float4* __restrict__ w,
                             const float4* __restrict__ pw)
{
    const float4* s; uint2 *hp, *lp; int n4;
    if (blockIdx.y == 0)      { s = x;  hp = (uint2*)g_xh;  lp = (uint2*)g_xl;  n4 = 1048576; }
    else if (blockIdx.y == 1) { s = w;  hp = (uint2*)g_wh;  lp = (uint2*)g_wl;  n4 = 786432; }
    else                      { s = pw; hp = (uint2*)g_pwh; lp = (uint2*)g_pwl; n4 = 262144; }
    for (int i = blockIdx.x * blockDim.x + threadIdx.x; i < n4; i += gridDim.x * blockDim.x) {
        float4 f = s[i];
        unsigned h0, l0, h1, l1;
        split2(f.x, f.y, h0, l0);
        split2(f.z, f.w, h1, l1);
        hp[i] = make_uint2(h0, h1);
        lp[i] = make_uint2(l0, l1);
    }
}

// ---------------- GEMM mainloop (pre-split operands, cp.async, ldmatrix) -------
// smem stage (words): Ah@0, Al@2560, Bh@5120, Bl@7680; row stride 20 words.
#define SWRD   10240
#define O_ALO  2560
#define O_BHI  5120
#define O_BLO  7680
#define GEMM_SMEM 81920

__device__ __forceinline__ void mainloop_pre(
    const unsigned* __restrict__ gAh, const unsigned* __restrict__ gAl,
    const unsigned* __restrict__ gBh, const unsigned* __restrict__ gBl,
    int row0, int col0, unsigned* u, float acc[4][4][4])
{
    const int tid = threadIdx.x;
    const int wid = tid >> 5, lane = tid & 31;
    const int wm = wid >> 2, wn = wid & 3;
    const int lq = lane >> 3, lr = lane & 7;
    const unsigned ub = smem_u32(u);

    int rr[2], kk[2], dof[2];
    #pragma unroll
    for (int v = 0; v < 2; v++) {
        int q = tid + 256 * v;         // 0..511 (512 float4 per array per chunk)
        rr[v] = q >> 2;
        kk[v] = (q & 3) << 2;
        dof[v] = rr[v] * 20 + kk[v];
    }
    const unsigned* aH = gAh + (size_t)row0 * 512;
    const unsigned* aL = gAl + (size_t)row0 * 512;
    const unsigned* bH = gBh + (size_t)col0 * 512;
    const unsigned* bL = gBl + (size_t)col0 * 512;

    // ldmatrix lane base addresses (bytes)
    const unsigned aBase = ub + (((64 * wm + (lq & 1) * 8 + lr) * 20 + (lq >> 1) * 4) << 2);
    const unsigned bBase = ub + ((O_BHI + (32 * wn + (lq >> 1) * 8 + lr) * 20 + (lq & 1) * 4) << 2);

    // fill chunk 0 into stage 0
    #pragma unroll
    for (int v = 0; v < 2; v++) {
        int so = rr[v] * 512 + kk[v];
        unsigned da = ub + (unsigned)(dof[v] << 2);
        cpa16(da,               aH + so);
        cpa16(da + O_ALO * 4,   aL + so);
        cpa16(da + O_BHI * 4,   bH + so);
        cpa16(da + O_BLO * 4,   bL + so);
    }
    CP_COMMIT();

    for (int c = 0; c < 32; c++) {
        if (c < 31) {
            const int s1 = (c + 1) & 1;
            #pragma unroll
            for (int v = 0; v < 2; v++) {
                int so = rr[v] * 512 + (c + 1) * 16 + kk[v];
                unsigned da = ub + (unsigned)((s1 * SWRD + dof[v]) << 2);
                cpa16(da,               aH + so);
                cpa16(da + O_ALO * 4,   aL + so);
                cpa16(da + O_BHI * 4,   bH + so);
                cpa16(da + O_BLO * 4,   bL + so);
            }
            CP_COMMIT();
            asm volatile("cp.async.wait_group 1;" ::: "memory");
        } else {
            asm volatile("cp.async.wait_group 0;" ::: "memory");
        }
        __syncthreads();

        const unsigned so = (unsigned)((c & 1) * (SWRD << 2));
        #pragma unroll
        for (int ks = 0; ks < 2; ks++) {
            unsigned bhf[2][4], blf[2][4];
            #pragma unroll
            for (int p = 0; p < 2; p++) {
                unsigned ad = bBase + so + (unsigned)((p * 320 + ks * 8) << 2);
                ldsm4(bhf[p][0], bhf[p][1], bhf[p][2], bhf[p][3], ad);
                ldsm4(blf[p][0], blf[p][1], blf[p][2], blf[p][3], ad + O_ALO * 4);
            }
            #pragma unroll
            for (int mi = 0; mi < 4; mi++) {
                unsigned ad = aBase + so + (unsigned)((mi * 320 + ks * 8) << 2);
                unsigned ah0, ah1, ah2, ah3, al0, al1, al2, al3;
                ldsm4(ah0, ah1, ah2, ah3, ad);
                ldsm4(al0, al1, al2, al3, ad + O_ALO * 4);
                #pragma unroll
                for (int ni = 0; ni < 4; ni++) {
                    const int p = ni >> 1, i0 = (ni & 1) * 2;
                    mma16816(acc[mi][ni], ah0, ah1, ah2, ah3, bhf[p][i0], bhf[p][i0+1]);
                    mma16816(acc[mi][ni], ah0, ah1, ah2, ah3, blf[p][i0], blf[p][i0+1]);
                    mma16816(acc[mi][ni], al0, al1, al2, al3, bhf[p][i0], bhf[p][i0+1]);
                }
            }
        }
        __syncthreads();
    }
}

// ---------------- Kernel 1: QKV GEMM + LN + RoPE + split-store ----------------
__global__ __launch_bounds__(256, 2) void qkv_mm(
    const float* __restrict__ qn_w, const float* __restrict__ qn_b,
    const float* __restrict__ kn_w, const float* __restrict__ kn_b)
{
    extern __shared__ __align__(16) unsigned u[];
    const int tid = threadIdx.x;
    const int wid = tid >> 5, lane = tid & 31;
    const int wm = wid >> 2, wn = wid & 3;
    const int grp = lane >> 2, qid = lane & 3;
    const int row0 = blockIdx.y * 128;
    const int col0 = blockIdx.x * 128;

    float acc[4][4][4];
    #pragma unroll
    for (int i = 0; i < 4; i++)
        #pragma unroll
        for (int j = 0; j < 4; j++)
            #pragma unroll
            for (int k = 0; k < 4; k++) acc[i][j][k] = 0.f;

    mainloop_pre(g_xh, g_xl, g_wh, g_wl, row0, col0, u, acc);

    // stage 128x128 f32 tile (stride 132)
    float* stg = (float*)u;
    #pragma unroll
    for (int mi = 0; mi < 4; mi++) {
        int rr2 = 64 * wm + 16 * mi + grp;
        #pragma unroll
        for (int ni = 0; ni < 4; ni++) {
            int cc = 32 * wn + 8 * ni + 2 * qid;
            stg[rr2 * 132 + cc]           = acc[mi][ni][0];
            stg[rr2 * 132 + cc + 1]       = acc[mi][ni][1];
            stg[(rr2 + 8) * 132 + cc]     = acc[mi][ni][2];
            stg[(rr2 + 8) * 132 + cc + 1] = acc[mi][ni][3];
        }
    }
    __syncthreads();

    const int hh = tid >> 7, r = tid & 127;
    float d[64];
    const float* src = stg + r * 132 + hh * 64;
    #pragma unroll
    for (int j = 0; j < 16; j++) {
        float4 v = *(const float4*)(src + 4 * j);
        d[4*j] = v.x; d[4*j+1] = v.y; d[4*j+2] = v.z; d[4*j+3] = v.w;
    }

    const int t = col0 >> 10;                      // 0=q,1=k,2=v
    const int h = ((col0 & 1023) >> 6) + hh;
    const int grow = row0 + r;
    const int b = grow >> 10, n = grow & 1023;
    const size_t wbase = ((size_t)(b * H_ + h) * N_ + n) * 32;   // word offset

    unsigned hw[32], lw2[32];
    if (t == 2) {
        #pragma unroll
        for (int cpair = 0; cpair < 32; cpair++)
            splitf16(d[2*cpair], d[2*cpair+1], hw[cpair], lw2[cpair]);
        #pragma unroll
        for (int q8 = 0; q8 < 8; q8++) {
            *(uint4*)(g_Vh + wbase + 4*q8) = make_uint4(hw[4*q8], hw[4*q8+1], hw[4*q8+2], hw[4*q8+3]);
            *(uint4*)(g_Vl + wbase + 4*q8) = make_uint4(lw2[4*q8], lw2[4*q8+1], lw2[4*q8+2], lw2[4*q8+3]);
        }
        return;
    }

    const float* lw = t ? kn_w : qn_w;
    const float* lb = t ? kn_b : qn_b;
    float s1 = 0.f, s2 = 0.f;
    #pragma unroll
    for (int j = 0; j < 64; j++) { s1 += d[j]; s2 += d[j] * d[j]; }
    float mu = s1 * (1.f / 64.f);
    float var = s2 * (1.f / 64.f) - mu * mu;
    float rstd = rsqrtf(var + 1e-5f);
    #pragma unroll
    for (int j = 0; j < 64; j++)
        d[j] = (d[j] - mu) * rstd * __ldg(lw + j) + __ldg(lb + j);
    #pragma unroll
    for (int j = 0; j < 32; j++) {
        float invf = expf(-(float)j * 0.2878231366242557f);   // 10000^(-j/32)
        float sn, cs;
        sincosf((float)n * invf, &sn, &cs);
        float t0 = d[j];
        d[j]      = t0 * cs - d[j + 32] * sn;
        d[j + 32] = d[j + 32] * cs + t0 * sn;
    }
    if (t == 0) {
        #pragma unroll
        for (int j = 0; j < 64; j++) d[j] *= QSCALE;           // fold sm_scale*log2e into Q
    }
    #pragma unroll
    for (int cpair = 0; cpair < 32; cpair++)
        split2(d[2*cpair], d[2*cpair+1], hw[cpair], lw2[cpair]);
    unsigned* dh = t ? g_Kh : g_Qh;
    unsigned* dl = t ? g_Kl : g_Ql;
    #pragma unroll
    for (int q8 = 0; q8 < 8; q8++) {
        *(uint4*)(dh + wbase + 4*q8) = make_uint4(hw[4*q8], hw[4*q8+1], hw[4*q8+2], hw[4*q8+3]);
        *(uint4*)(dl + wbase + 4*q8) = make_uint4(lw2[4*q8], lw2[4*q8+1], lw2[4*q8+2], lw2[4*q8+3]);
    }
}

// ---------------- Kernel 3: proj GEMM + bias ----------------
__global__ __launch_bounds__(256, 2) void proj_mm(
    const float* __restrict__ bias, float* __restrict__ out)
{
    extern __shared__ __align__(16) unsigned u[];
    const int tid = threadIdx.x;
    const int wid = tid >> 5, lane = tid & 31;
    const int wm = wid >> 2, wn = wid & 3;
    const int grp = lane >> 2, qid = lane & 3;
    const int row0 = blockIdx.y * 128;
    const int col0 = blockIdx.x * 128;

    float acc[4][4][4];
    #pragma unroll
    for (int i = 0; i < 4; i++)
        #pragma unroll
        for (int j = 0; j < 4; j++)
            #pragma unroll
            for (int k = 0; k < 4; k++) acc[i][j][k] = 0.f;

    mainloop_pre(g_AOh, g_AOl, g_pwh, g_pwl, row0, col0, u, acc);

    #pragma unroll
    for (int mi = 0; mi < 4; mi++) {
        int rr = row0 + 64 * wm + 16 * mi + grp;
        #pragma unroll
        for (int ni = 0; ni < 4; ni++) {
            int cc = col0 + 32 * wn + 8 * ni + 2 * qid;
            float b0 = __ldg(bias + cc), b1 = __ldg(bias + cc + 1);
            *(float2*)(out + (size_t)rr * DIM_ + cc) =
                make_float2(acc[mi][ni][0] + b0, acc[mi][ni][1] + b1);
            *(float2*)(out + (size_t)(rr + 8) * DIM_ + cc) =
                make_float2(acc[mi][ni][2] + b0, acc[mi][ni][3] + b1);
        }
    }
}

// ---------------- Kernel 2: tensor-core flash attention (ldmatrix) -------------
// smem word offsets: Qh,Ql,Kh,Kl,Vh,Vl each 64 rows x 36 words
#define AQH 0
#define AQL 2304
#define AKH 4608
#define AKL 6912
#define AVH 9216
#define AVL 11520
#define ATT_SMEM 55296

__global__ __launch_bounds__(128) void attn_tc(const float* __restrict__ sinks)
{
    extern __shared__ __align__(16) unsigned u[];
    const int tid = threadIdx.x;
    const int wid = tid >> 5, lane = tid & 31;
    const int g8 = lane >> 2, qid = lane & 3;
    const int lq = lane >> 3, lr = lane & 7;
    const int bh = blockIdx.y, b = bh >> 4, h = bh & 15;
    const int q0 = blockIdx.x * 64;
    const unsigned ub = smem_u32(u);

    const size_t base = (size_t)(b * H_ + h) * N_ * 32;   // word base of this (b,h)
    const unsigned* Qhg = g_Qh + base + (size_t)q0 * 32;
    const unsigned* Qlg = g_Ql + base + (size_t)q0 * 32;
    const unsigned* Khg = g_Kh + base;
    const unsigned* Klg = g_Kl + base;
    const unsigned* Vhg = g_Vh + base;
    const unsigned* Vlg = g_Vl + base;

    #pragma unroll
    for (int v = 0; v < 4; v++) {
        int idx = tid + 128 * v;          // 0..511
        int r = idx >> 3, f = idx & 7;
        *(uint4*)(u + AQH + r * 36 + f * 4) = *(const uint4*)(Qhg + r * 32 + f * 4);
        *(uint4*)(u + AQL + r * 36 + f * 4) = *(const uint4*)(Qlg + r * 32 + f * 4);
    }
    __syncthreads();

    // hoist Q fragments (loop-invariant over kt)
    unsigned qh[4][4], ql[4][4];
    const unsigned qBase = ub + ((AQH + (16 * wid + (lq & 1) * 8 + lr) * 36 + (lq >> 1) * 4) << 2);
    #pragma unroll
    for (int ks = 0; ks < 4; ks++) {
        ldsm4(qh[ks][0], qh[ks][1], qh[ks][2], qh[ks][3], qBase + (unsigned)((ks * 8) << 2));
        ldsm4(ql[ks][0], ql[ks][1], ql[ks][2], ql[ks][3],
              qBase + (unsigned)((AQL - AQH + ks * 8) << 2));
    }

    const unsigned kBase = ub + ((AKH + ((lq >> 1) * 8 + lr) * 36 + (lq & 1) * 4) << 2);
    const unsigned vBase = ub + ((AVH + ((lq & 1) * 8 + lr) * 36 + (lq >> 1) * 4) << 2);

    float m0 = __ldg(sinks + h) * LOG2E, m1 = m0;
    float d0 = 1.f, d1 = 1.f;
    float oacc[8][4];
    #pragma unroll
    for (int i = 0; i < 8; i++)
        #pragma unroll
        for (int j = 0; j < 4; j++) oacc[i][j] = 0.f;

    const int i0 = q0 + 16 * wid + g8;
    const int i1 = i0 + 8;
    const int kt_lo = (q0 >= SW_) ? ((q0 - SW_ + 1) >> 6) : 0;
    const int kt_hi = q0 >> 6;

    for (int kt = kt_lo; kt <= kt_hi; kt++) {
        const int k0 = kt << 6;
        __syncthreads();
        #pragma unroll
        for (int v = 0; v < 4; v++) {
            int idx = tid + 128 * v;
            int r = idx >> 3, f = idx & 7;
            *(uint4*)(u + AKH + r * 36 + f * 4) = *(const uint4*)(Khg + (k0 + r) * 32 + f * 4);
            *(uint4*)(u + AKL + r * 36 + f * 4) = *(const uint4*)(Klg + (k0 + r) * 32 + f * 4);
            *(uint4*)(u + AVH + r * 36 + f * 4) = *(const uint4*)(Vhg + (k0 + r) * 32 + f * 4);
            *(uint4*)(u + AVL + r * 36 + f * 4) = *(const uint4*)(Vlg + (k0 + r) * 32 + f * 4);
        }
        __syncthreads();

        // S = Q K^T (bf16 3-pass, base-2 logits)
        float sacc[8][4];
        #pragma unroll
        for (int i = 0; i < 8; i++)
            #pragma unroll
            for (int j = 0; j < 4; j++) sacc[i][j] = 0.f;

        #pragma unroll
        for (int ks = 0; ks < 4; ks++) {
            #pragma unroll
            for (int p = 0; p < 4; p++) {
                unsigned kh0, kh1, kh2, kh3, kl0, kl1, kl2, kl3;
                unsigned ad = kBase + (unsigned)((p * 576 + ks * 8) << 2);
                ldsm4(kh0, kh1, kh2, kh3, ad);
                ldsm4(kl0, kl1, kl2, kl3, ad + (unsigned)((AKL - AKH) << 2));
                mma16816(sacc[2*p],   qh[ks][0], qh[ks][1], qh[ks][2], qh[ks][3], kh0, kh1);
                mma16816(sacc[2*p],   qh[ks][0], qh[ks][1], qh[ks][2], qh[ks][3], kl0, kl1);
                mma16816(sacc[2*p],   ql[ks][0], ql[ks][1], ql[ks][2], ql[ks][3], kh0, kh1);
                mma16816(sacc[2*p+1], qh[ks][0], qh[ks][1], qh[ks][2], qh[ks][3], kh2, kh3);
                mma16816(sacc[2*p+1], qh[ks][0], qh[ks][1], qh[ks][2], qh[ks][3], kl2, kl3);
                mma16816(sacc[2*p+1], ql[ks][0], ql[ks][1], ql[ks][2], ql[ks][3], kh2, kh3);
            }
        }

        // mask + row max
        float mx0 = -1e30f, mx1 = -1e30f;
        #pragma unroll
        for (int ni = 0; ni < 8; ni++) {
            int j = k0 + 8 * ni + 2 * qid;
            sacc[ni][0] = (j     <= i0 && j     > i0 - SW_) ? sacc[ni][0] : -1e30f;
            sacc[ni][1] = (j + 1 <= i0 && j + 1 > i0 - SW_) ? sacc[ni][1] : -1e30f;
            sacc[ni][2] = (j     <= i1 && j     > i1 - SW_) ? sacc[ni][2] : -1e30f;
            sacc[ni][3] = (j + 1 <= i1 && j + 1 > i1 - SW_) ? sacc[ni][3] : -1e30f;
            mx0 = fmaxf(mx0, fmaxf(sacc[ni][0], sacc[ni][1]));
            mx1 = fmaxf(mx1, fmaxf(sacc[ni][2], sacc[ni][3]));
        }
        mx0 = fmaxf(mx0, __shfl_xor_sync(0xffffffffu, mx0, 1));
        mx0 = fmaxf(mx0, __shfl_xor_sync(0xffffffffu, mx0, 2));
        mx1 = fmaxf(mx1, __shfl_xor_sync(0xffffffffu, mx1, 1));
        mx1 = fmaxf(mx1, __shfl_xor_sync(0xffffffffu, mx1, 2));
        float mn0 = fmaxf(m0, mx0), mn1 = fmaxf(m1, mx1);
        float sc0 = ex2f(m0 - mn0), sc1 = ex2f(m1 - mn1);
        m0 = mn0; m1 = mn1; d0 *= sc0; d1 *= sc1;
        #pragma unroll
        for (int nd = 0; nd < 8; nd++) {
            oacc[nd][0] *= sc0; oacc[nd][1] *= sc0;
            oacc[nd][2] *= sc1; oacc[nd][3] *= sc1;
        }

        // e = 2^(s-m), split to f16 hi/lo; accumulate row sums
        unsigned pfh[8][2], pfl[8][2];
        float t0 = 0.f, t1 = 0.f;
        #pragma unroll
        for (int ni = 0; ni < 8; ni++) {
            float e0 = ex2f(fmaxf(sacc[ni][0] - mn0, -126.f));
            float e1 = ex2f(fmaxf(sacc[ni][1] - mn0, -126.f));
            float e2 = ex2f(fmaxf(sacc[ni][2] - mn1, -126.f));
            float e3 = ex2f(fmaxf(sacc[ni][3] - mn1, -126.f));
            t0 += e0 + e1; t1 += e2 + e3;
            splitf16(e0, e1, pfh[ni][0], pfl[ni][0]);
            splitf16(e2, e3, pfh[ni][1], pfl[ni][1]);
        }
        t0 += __shfl_xor_sync(0xffffffffu, t0, 1);
        t0 += __shfl_xor_sync(0xffffffffu, t0, 2);
        t1 += __shfl_xor_sync(0xffffffffu, t1, 1);
        t1 += __shfl_xor_sync(0xffffffffu, t1, 2);
        d0 += t0; d1 += t1;

        // O += P V (f16: Phi*Vhi + Phi*Vlo + Plo*Vhi), V frags via ldmatrix.trans
        #pragma unroll
        for (int kf = 0; kf < 4; kf++) {
            unsigned a0 = pfh[2*kf][0], a1 = pfh[2*kf][1];
            unsigned a2 = pfh[2*kf+1][0], a3 = pfh[2*kf+1][1];
            unsigned c0 = pfl[2*kf][0], c1 = pfl[2*kf][1];
            unsigned c2 = pfl[2*kf+1][0], c3 = pfl[2*kf+1][1];
            #pragma unroll
            for (int p = 0; p < 4; p++) {
                unsigned vh0, vh1, vh2, vh3, vl0, vl1, vl2, vl3;
                unsigned ad = vBase + (unsigned)((kf * 576 + p * 8) << 2);
                ldsm4t(vh0, vh1, vh2, vh3, ad);
                ldsm4t(vl0, vl1, vl2, vl3, ad + (unsigned)((AVL - AVH) << 2));
                mma16816h(oacc[2*p],   a0, a1, a2, a3, vh0, vh1);
                mma16816h(oacc[2*p],   a0, a1, a2, a3, vl0, vl1);
                mma16816h(oacc[2*p],   c0, c1, c2, c3, vh0, vh1);
                mma16816h(oacc[2*p+1], a0, a1, a2, a3, vh2, vh3);
                mma16816h(oacc[2*p+1], a0, a1, a2, a3, vl2, vl3);
                mma16816h(oacc[2*p+1], c0, c1, c2, c3, vh2, vh3);
            }
        }
    }

    // epilogue: AO[b*N + i, 64h + d] split bf16
    float inv0 = 1.f / d0, inv1 = 1.f / d1;
    #pragma unroll
    for (int nd = 0; nd < 8; nd++) {
        int col = 64 * h + 8 * nd + 2 * qid;
        unsigned hi, lo;
        split2(oacc[nd][0] * inv0, oacc[nd][1] * inv0, hi, lo);
        size_t w0 = ((size_t)(b * N_ + i0)) * 512 + (col >> 1);
        g_AOh[w0] = hi; g_AOl[w0] = lo;
        split2(oacc[nd][2] * inv1, oacc[nd][3] * inv1, hi, lo);
        size_t w1 = ((size_t)(b * N_ + i1)) * 512 + (col >> 1);
        g_AOh[w1] = hi; g_AOl[w1] = lo;
    }
}

extern "C" void kernel_launch(void* const* d_in, const int* in_sizes, int n_in,
                              void* d_out, int out_size)
{
    const float* x      = (const float*)d_in[0];
    const float* qkv_w  = (const float*)d_in[1];
    const float* qn_w   = (const float*)d_in[2];
    const float* qn_b   = (const float*)d_in[3];
    const float* kn_w   = (const float*)d_in[4];
    const float* kn_b   = (const float*)d_in[5];
    const float* sinks  = (const float*)d_in[6];
    const float* proj_w = (const float*)d_in[7];
    const float* proj_b = (const float*)d_in[8];
    float* out = (float*)d_out;

    cudaFuncSetAttribute(qkv_mm,  cudaFuncAttributeMaxDynamicSharedMemorySize, GEMM_SMEM);
    cudaFuncSetAttribute(proj_mm, cudaFuncAttributeMaxDynamicSharedMemorySize, GEMM_SMEM);
    cudaFuncSetAttribute(attn_tc, cudaFuncAttributeMaxDynamicSharedMemorySize, ATT_SMEM);

    presplit_all<<<dim3(1024, 3), 256>>>((const float4*)x, (const float4*)qkv_w,
                                         (const float4*)proj_w);
    qkv_mm<<<dim3(24, 32), 256, GEMM_SMEM>>>(qn_w, qn_b, kn_w, kn_b);
    attn_tc<<<dim3(16, 64), 128, ATT_SMEM>>>(sinks);
    proj_mm<<<dim3(8, 32), 256, GEMM_SMEM>>>(proj_b, out);
}